// round 1
// baseline (speedup 1.0000x reference)
#include <cuda_runtime.h>

// Depthwise cross-correlation (no kernel flip, XLA conv semantics):
//   out[ch, ho, wo] = sum_{ky<7, kx<7} x[ch, ho+ky, wo+kx] * z[ch, ky, kx]
// x: [32768, 31, 31], z: [32768, 7, 7], out: [32768, 25, 25], all fp32.

#define HX 31
#define WX 31
#define HZ 7
#define WZ 7
#define HO 25
#define WO 25
#define XPAD 32          // padded x row stride (floats); col 31 zero-filled
#define CH_PER_CTA 4
#define NCH (128 * 256)

__device__ __forceinline__ void fma2(unsigned long long &d,
                                     unsigned long long a,
                                     unsigned long long b) {
    // packed f32x2 FMA (Blackwell sm_100+): d.lo += a.lo*b.lo; d.hi += a.hi*b.hi
    asm("fma.rn.f32x2 %0, %1, %2, %0;" : "+l"(d) : "l"(a), "l"(b));
}

__global__ void __launch_bounds__(128)
dwxcorr_f32x2_kernel(const float* __restrict__ zf,
                     const float* __restrict__ xf,
                     float* __restrict__ out) {
    __shared__ float sx[CH_PER_CTA][HX][XPAD];
    __shared__ float sk[CH_PER_CTA][2][HZ][8];   // [parity][ky][padded taps]

    const int warp = threadIdx.x >> 5;
    const int lane = threadIdx.x & 31;
    const int ch   = blockIdx.x * CH_PER_CTA + warp;

    const float* __restrict__ xch = xf + (long long)ch * (HX * WX);
    const float* __restrict__ zch = zf + (long long)ch * (HZ * WZ);

    // ---- stage x tile into padded smem (whole warp) ----
    for (int i = lane; i < HX * WX; i += 32) {
        int r = i / WX;
        int c = i - r * WX;
        sx[warp][r][c] = xch[i];
    }
    if (lane < HX) sx[warp][lane][WX] = 0.0f;    // zero pad column 31

    // ---- stage kernel, two parity-shifted zero-padded copies ----
    // even copy: [k0 k1 k2 k3 k4 k5 k6 0]
    // odd  copy: [0  k0 k1 k2 k3 k4 k5 k6]
    for (int i = lane; i < HZ * 8; i += 32) {
        int ky = i >> 3;
        int j  = i & 7;
        sk[warp][0][ky][j] = (j < WZ) ? zch[ky * WZ + j] : 0.0f;
        sk[warp][1][ky][j] = (j >= 1) ? zch[ky * WZ + (j - 1)] : 0.0f;
    }
    __syncwarp();

    if (lane >= WO) return;                      // 25 active lanes per warp

    const int wo  = lane;
    const int par = wo & 1;
    const int x0  = wo & ~1;                     // even-aligned pair base

    // kernel tap pairs for this parity -> registers (28 x f32x2)
    unsigned long long kk[HZ][4];
#pragma unroll
    for (int ky = 0; ky < HZ; ky++) {
#pragma unroll
        for (int j = 0; j < 4; j++) {
            kk[ky][j] = *reinterpret_cast<const unsigned long long*>(
                &sk[warp][par][ky][2 * j]);
        }
    }

    unsigned long long acc[HO];                  // f32x2 accumulators, one per output row
#pragma unroll
    for (int i = 0; i < HO; i++) acc[i] = 0ULL;

    // walk the 31 x rows once; each row feeds up to 7 output rows
#pragma unroll
    for (int r = 0; r < HX; r++) {
        const unsigned long long p0 =
            *reinterpret_cast<const unsigned long long*>(&sx[warp][r][x0 + 0]);
        const unsigned long long p1 =
            *reinterpret_cast<const unsigned long long*>(&sx[warp][r][x0 + 2]);
        const unsigned long long p2 =
            *reinterpret_cast<const unsigned long long*>(&sx[warp][r][x0 + 4]);
        const unsigned long long p3 =
            *reinterpret_cast<const unsigned long long*>(&sx[warp][r][x0 + 6]);
#pragma unroll
        for (int ky = 0; ky < HZ; ky++) {
            const int ho = r - ky;
            if (ho >= 0 && ho < HO) {
                fma2(acc[ho], p0, kk[ky][0]);
                fma2(acc[ho], p1, kk[ky][1]);
                fma2(acc[ho], p2, kk[ky][2]);
                fma2(acc[ho], p3, kk[ky][3]);
            }
        }
    }

    float* __restrict__ och = out + (long long)ch * (HO * WO);
#pragma unroll
    for (int ho = 0; ho < HO; ho++) {
        float2 v = *reinterpret_cast<float2*>(&acc[ho]);
        och[ho * WO + wo] = v.x + v.y;
    }
}

extern "C" void kernel_launch(void* const* d_in, const int* in_sizes, int n_in,
                              void* d_out, int out_size) {
    // metadata order: z_f [128,256,7,7] then x_f [128,256,31,31]
    const float* z = (const float*)d_in[0];
    const float* x = (const float*)d_in[1];
    if (n_in >= 2 && in_sizes[0] > in_sizes[1]) {   // defensive: z is the small one
        const float* t = z; z = x; x = t;
    }
    float* o = (float*)d_out;

    dim3 grid(NCH / CH_PER_CTA);
    dim3 block(128);
    dwxcorr_f32x2_kernel<<<grid, block>>>(z, x, o);
}